// round 13
// baseline (speedup 1.0000x reference)
#include <cuda_runtime.h>
#include <cuda_fp16.h>
#include <stdint.h>
#include <math.h>

#define NE 8
#define HID 2048
#define INTER 1408
#define TOT 8192
#define MAXTILES 96
#define MAXGRIDY 72

// ---------------------------------------------------------------------------
// Device globals (fp16 single plane everywhere)
// ---------------------------------------------------------------------------
__device__ int g_tile_expert[MAXTILES];
__device__ int g_tile_row0[MAXTILES];
__device__ int g_tile_nrows[MAXTILES];
__device__ int g_ntiles;

__device__ __half g_x[(size_t)TOT * HID];
// transposed weights: [E][N][K], K contiguous
__device__ __half g_wg[(size_t)NE * INTER * HID];
__device__ __half g_wu[(size_t)NE * INTER * HID];
__device__ __half g_wd[(size_t)NE * HID * INTER];
__device__ __half g_h[(size_t)TOT * INTER];

// ---------------------------------------------------------------------------
// Helpers (base-target PTX: mma.sync sm_80, cp.async sm_80, ldmatrix sm_75)
// ---------------------------------------------------------------------------
__device__ __forceinline__ uint32_t smem_u32(const void* p) {
    uint32_t a;
    asm("{ .reg .u64 t; cvta.to.shared.u64 t, %1; cvt.u32.u64 %0, t; }"
        : "=r"(a) : "l"(p));
    return a;
}

__device__ __forceinline__ void cp16(uint32_t dst, const void* src, int srcsize) {
    asm volatile("cp.async.cg.shared.global [%0], [%1], 16, %2;"
                 :: "r"(dst), "l"(src), "r"(srcsize));
}
#define CP_COMMIT() asm volatile("cp.async.commit_group;")
#define CP_WAIT0()  asm volatile("cp.async.wait_group 0;")

// fp16-accumulate HMMA: D(fp16x2 x2) = A*B + C
__device__ __forceinline__ void mma16816h(uint32_t& d0, uint32_t& d1,
                                          const uint32_t a[4], const uint32_t* b) {
    asm volatile(
        "mma.sync.aligned.m16n8k16.row.col.f16.f16.f16.f16 "
        "{%0,%1},{%2,%3,%4,%5},{%6,%7},{%0,%1};"
        : "+r"(d0), "+r"(d1)
        : "r"(a[0]), "r"(a[1]), "r"(a[2]), "r"(a[3]), "r"(b[0]), "r"(b[1]));
}
#define MMAH(D, A, B) mma16816h((D)[0], (D)[1], (A), (B))

__device__ __forceinline__ void ldm_x4(uint32_t r[4], uint32_t addr) {
    asm volatile("ldmatrix.sync.aligned.m8n8.x4.shared.b16 {%0,%1,%2,%3}, [%4];"
                 : "=r"(r[0]), "=r"(r[1]), "=r"(r[2]), "=r"(r[3]) : "r"(addr));
}

// spill one fp16 m16n8 accumulator tile into 4 fp32 accumulators
__device__ __forceinline__ void spill(float* c, const uint32_t d[2]) {
    float2 lo = __half22float2(*(const __half2*)&d[0]);
    float2 hi = __half22float2(*(const __half2*)&d[1]);
    c[0] += lo.x; c[1] += lo.y; c[2] += hi.x; c[3] += hi.y;
}

// Row stride 80 B (conflict-free for cp.async stores and ldmatrix reads)
#define RSTR 80

// A fragment group (16 rows x 16 k): one ldmatrix.x4 -> mma operand order
__device__ __forceinline__ void fragA(uint32_t a[4], uint32_t tile, int rb, int k0, int lane) {
    uint32_t addr = tile + (uint32_t)(rb + (lane & 15)) * RSTR
                         + (uint32_t)(k0 + (lane >> 4) * 8) * 2;
    ldm_x4(a, addr);
}
// B fragment pair (two adjacent n-octets x 16 k from [n][k] tile)
__device__ __forceinline__ void fragB2(uint32_t b[4], uint32_t tile, int nb, int k0, int lane) {
    uint32_t addr = tile + (uint32_t)(nb + ((lane >> 4) * 8) + (lane & 7)) * RSTR
                         + (uint32_t)(k0 + ((lane >> 3) & 1) * 8) * 2;
    ldm_x4(b, addr);
}

// 128-row x 32-col fp16 tile via cp.async; per-thread sizes precomputed
__device__ __forceinline__ void load_tile128(uint32_t sdst, const __half* src,
                                             int ldk, int k0, int s0, int s1, int tid) {
    const int r = tid >> 2, c = tid & 3;
    cp16(sdst + r * RSTR + c * 16, src + (size_t)r * ldk + k0 + c * 8, s0);
    cp16(sdst + (r + 64) * RSTR + c * 16, src + (size_t)(r + 64) * ldk + k0 + c * 8, s1);
}
__device__ __forceinline__ void load_tile64(uint32_t sdst, const __half* src,
                                            int ldk, int k0, int tid) {
    const int r = tid >> 2, c = tid & 3;
    cp16(sdst + r * RSTR + c * 16, src + (size_t)r * ldk + k0 + c * 8, 16);
}

// ---------------------------------------------------------------------------
// Prep kernels
// ---------------------------------------------------------------------------
__global__ void convert_x(const float* __restrict__ x, const int* __restrict__ tpe) {
    if (blockIdx.x == 0 && threadIdx.x == 0) {
        int off = 0, nt = 0;
        for (int e = 0; e < NE; e++) {
            int n = tpe[e];
            for (int r = 0; r < n; r += 128) {
                g_tile_expert[nt] = e;
                g_tile_row0[nt]   = off + r;
                g_tile_nrows[nt]  = (n - r < 128) ? (n - r) : 128;
                nt++;
            }
            off += n;
        }
        g_ntiles = nt;
    }
    const size_t n4 = (size_t)TOT * HID / 4;
    for (size_t i = blockIdx.x * blockDim.x + threadIdx.x; i < n4;
         i += (size_t)gridDim.x * blockDim.x) {
        float4 v = ((const float4*)x)[i];
        __half2 p0 = __floats2half2_rn(v.x, v.y);
        __half2 p1 = __floats2half2_rn(v.z, v.w);
        ((uint2*)g_x)[i] = make_uint2(*(uint32_t*)&p0, *(uint32_t*)&p1);
    }
}

// z<NE: wg, z>=NE: wu.  [E][HID][INTER] fp32 -> [E][INTER][HID] fp16.
__global__ void transpose_cvt_gu(const float* __restrict__ wg,
                                 const float* __restrict__ wu) {
    __shared__ float t[32][33];
    const int z = blockIdx.z;
    const int e = z & (NE - 1);
    const bool isu = z >= NE;
    const float* src = (isu ? wu : wg) + (size_t)e * HID * INTER;
    __half* dst = (isu ? g_wu : g_wg) + (size_t)e * HID * INTER;
    const int k0 = blockIdx.x * 32, n0 = blockIdx.y * 32;
    const int tx = threadIdx.x, ty = threadIdx.y;
#pragma unroll
    for (int jj = 0; jj < 2; jj++) {
        const int kl = ty + jj * 16;
        float2 v = *(const float2*)(src + (size_t)(k0 + kl) * INTER + n0 + 2 * tx);
        t[kl][2 * tx] = v.x;
        t[kl][2 * tx + 1] = v.y;
    }
    __syncthreads();
#pragma unroll
    for (int jj = 0; jj < 2; jj++) {
        const int nl = ty + jj * 16;
        __half2 p = __floats2half2_rn(t[2 * tx][nl], t[2 * tx + 1][nl]);
        *(uint32_t*)(dst + (size_t)(n0 + nl) * HID + k0 + 2 * tx) = *(uint32_t*)&p;
    }
}

// [E][INTER][HID] fp32 -> [E][HID][INTER] fp16
__global__ void transpose_cvt_d(const float* __restrict__ wd) {
    __shared__ float t[32][33];
    const int e = blockIdx.z;
    const float* src = wd + (size_t)e * INTER * HID;
    __half* dst = g_wd + (size_t)e * INTER * HID;
    const int k0 = blockIdx.x * 32, n0 = blockIdx.y * 32;
    const int tx = threadIdx.x, ty = threadIdx.y;
#pragma unroll
    for (int jj = 0; jj < 2; jj++) {
        const int kl = ty + jj * 16;
        float2 v = *(const float2*)(src + (size_t)(k0 + kl) * HID + n0 + 2 * tx);
        t[kl][2 * tx] = v.x;
        t[kl][2 * tx + 1] = v.y;
    }
    __syncthreads();
#pragma unroll
    for (int jj = 0; jj < 2; jj++) {
        const int nl = ty + jj * 16;
        __half2 p = __floats2half2_rn(t[2 * tx][nl], t[2 * tx + 1][nl]);
        *(uint32_t*)(dst + (size_t)(n0 + nl) * INTER + k0 + 2 * tx) = *(uint32_t*)&p;
    }
}

// ---------------------------------------------------------------------------
// Fused gate+up grouped GEMM (fp16, fp16-accum + per-chunk fp32 spill).
// CTA: M=128 x N=64 (per matrix), BK=64 (two 32-k sub-tiles per stage).
// 8 warps (4M x 2N), warp 32x32 per matrix. 2-stage, 1 barrier per chunk.
// Per chunk: gate pass (fp16 acc, 32 MMAs, spill) then up pass.
// Stage (40960 B): A sub0 0, A sub1 10240, G sub0 20480, G sub1 25600,
//                  U sub0 30720, U sub1 35840
// ---------------------------------------------------------------------------
#define GU_BUF 40960
#define GU_SMEM (2 * GU_BUF)

__global__ void __launch_bounds__(256) k_gateup() {
    const int t = blockIdx.y;
    if (t >= g_ntiles) return;
    const int e     = __ldg(&g_tile_expert[t]);
    const int row0  = __ldg(&g_tile_row0[t]);
    const int nrows = __ldg(&g_tile_nrows[t]);
    const int n0    = blockIdx.x * 64;

    extern __shared__ char smem[];
    const uint32_t sb = smem_u32(smem);
    const int tid  = threadIdx.x;
    const int lane = tid & 31;
    const int wid  = tid >> 5;
    const int wm   = wid & 3;
    const int wn   = wid >> 2;
    const int s0 = ((tid >> 2) < nrows) ? 16 : 0;
    const int s1 = ((tid >> 2) + 64 < nrows) ? 16 : 0;

    const __half* xp = g_x + (size_t)row0 * HID;
    const size_t wbase = (size_t)e * INTER * HID + (size_t)n0 * HID;
    const __half* gp = g_wg + wbase;
    const __half* up = g_wu + wbase;

    float cg[2][4][4], cu[2][4][4];
#pragma unroll
    for (int i = 0; i < 2; i++)
#pragma unroll
        for (int j = 0; j < 4; j++)
#pragma unroll
            for (int k = 0; k < 4; k++) { cg[i][j][k] = 0.f; cu[i][j][k] = 0.f; }

#define GU_LOAD(b, k0)                                                  \
    do {                                                                \
        uint32_t o = sb + (b) * GU_BUF;                                 \
        load_tile128(o,         xp, HID, (k0),      s0, s1, tid);       \
        load_tile128(o + 10240, xp, HID, (k0) + 32, s0, s1, tid);       \
        load_tile64(o + 20480,  gp, HID, (k0),      tid);               \
        load_tile64(o + 25600,  gp, HID, (k0) + 32, tid);               \
        load_tile64(o + 30720,  up, HID, (k0),      tid);               \
        load_tile64(o + 35840,  up, HID, (k0) + 32, tid);               \
        CP_COMMIT();                                                    \
    } while (0)

    GU_LOAD(0, 0);
    const int KC = HID / 64;   // 32 chunks
    for (int kc = 0; kc < KC; kc++) {
        CP_WAIT0();
        __syncthreads();
        if (kc + 1 < KC) GU_LOAD((kc + 1) & 1, (kc + 1) * 64);
        const uint32_t buf = sb + (kc & 1) * GU_BUF;

        // ---- gate pass (fp16 accum over this 64-k chunk) ----
        uint32_t ha[2][4][2];
#pragma unroll
        for (int i = 0; i < 2; i++)
#pragma unroll
            for (int j = 0; j < 4; j++) { ha[i][j][0] = 0u; ha[i][j][1] = 0u; }
#pragma unroll
        for (int ks = 0; ks < 4; ks++) {
            const int sub = ks >> 1;
            const int k0  = (ks & 1) * 16;
            const uint32_t bufA = buf + sub * 10240;
            const uint32_t bufG = buf + 20480 + sub * 5120;
            uint32_t A0[4], A1[4];
            fragA(A0, bufA, wm * 32,      k0, lane);
            fragA(A1, bufA, wm * 32 + 16, k0, lane);
#pragma unroll
            for (int p = 0; p < 2; p++) {
                uint32_t Bg[4];
                fragB2(Bg, bufG, wn * 32 + p * 16, k0, lane);
                const int q = p * 2;
                MMAH(ha[0][q],   A0, Bg);
                MMAH(ha[1][q],   A1, Bg);
                MMAH(ha[0][q+1], A0, Bg + 2);
                MMAH(ha[1][q+1], A1, Bg + 2);
            }
        }
#pragma unroll
        for (int i = 0; i < 2; i++)
#pragma unroll
            for (int j = 0; j < 4; j++) spill(cg[i][j], ha[i][j]);

        // ---- up pass ----
#pragma unroll
        for (int i = 0; i < 2; i++)
#pragma unroll
            for (int j = 0; j < 4; j++) { ha[i][j][0] = 0u; ha[i][j][1] = 0u; }
#pragma unroll
        for (int ks = 0; ks < 4; ks++) {
            const int sub = ks >> 1;
            const int k0  = (ks & 1) * 16;
            const uint32_t bufA = buf + sub * 10240;
            const uint32_t bufU = buf + 30720 + sub * 5120;
            uint32_t A0[4], A1[4];
            fragA(A0, bufA, wm * 32,      k0, lane);
            fragA(A1, bufA, wm * 32 + 16, k0, lane);
#pragma unroll
            for (int p = 0; p < 2; p++) {
                uint32_t Bu[4];
                fragB2(Bu, bufU, wn * 32 + p * 16, k0, lane);
                const int q = p * 2;
                MMAH(ha[0][q],   A0, Bu);
                MMAH(ha[1][q],   A1, Bu);
                MMAH(ha[0][q+1], A0, Bu + 2);
                MMAH(ha[1][q+1], A1, Bu + 2);
            }
        }
#pragma unroll
        for (int i = 0; i < 2; i++)
#pragma unroll
            for (int j = 0; j < 4; j++) spill(cu[i][j], ha[i][j]);
    }

    // epilogue: silu(gate)*up -> h (fp16)
#pragma unroll
    for (int mt = 0; mt < 2; mt++)
#pragma unroll
        for (int half = 0; half < 2; half++) {
            const int r = wm * 32 + mt * 16 + half * 8 + (lane >> 2);
            if (r < nrows) {
                __half* hp = g_h + (size_t)(row0 + r) * INTER + n0 + wn * 32;
#pragma unroll
                for (int nt = 0; nt < 4; nt++) {
                    const float gg0 = cg[mt][nt][half * 2], gg1 = cg[mt][nt][half * 2 + 1];
                    const float uu0 = cu[mt][nt][half * 2], uu1 = cu[mt][nt][half * 2 + 1];
                    const float h0 = uu0 * gg0 / (1.f + __expf(-gg0));
                    const float h1 = uu1 * gg1 / (1.f + __expf(-gg1));
                    __half2 p = __floats2half2_rn(h0, h1);
                    *(uint32_t*)(hp + nt * 8 + (lane & 3) * 2) = *(uint32_t*)&p;
                }
            }
        }
}

// ---------------------------------------------------------------------------
// Down grouped GEMM (fp16, fp16-accum + per-chunk fp32 spill).
// CTA: M=128 x N=128, BK=64. 8 warps (4x2), warp 32x64.
// Stage (40960 B): A sub0 0, A sub1 10240, B sub0 20480, B sub1 30720
// ---------------------------------------------------------------------------
#define DN_BUF 40960
#define DN_SMEM (2 * DN_BUF)

__global__ void __launch_bounds__(256) k_down(const float* __restrict__ probs,
                                              float* __restrict__ out) {
    const int t = blockIdx.y;
    if (t >= g_ntiles) return;
    const int e     = __ldg(&g_tile_expert[t]);
    const int row0  = __ldg(&g_tile_row0[t]);
    const int nrows = __ldg(&g_tile_nrows[t]);
    const int n0    = blockIdx.x * 128;

    extern __shared__ char smem[];
    const uint32_t sb = smem_u32(smem);
    const int tid  = threadIdx.x;
    const int lane = tid & 31;
    const int wid  = tid >> 5;
    const int wm   = wid & 3;
    const int wn   = wid >> 2;
    const int s0 = ((tid >> 2) < nrows) ? 16 : 0;
    const int s1 = ((tid >> 2) + 64 < nrows) ? 16 : 0;

    const __half* ap = g_h + (size_t)row0 * INTER;
    const size_t wbase = (size_t)e * HID * INTER + (size_t)n0 * INTER;
    const __half* bp = g_wd + wbase;

    float cc[2][8][4];
#pragma unroll
    for (int i = 0; i < 2; i++)
#pragma unroll
        for (int j = 0; j < 8; j++)
#pragma unroll
            for (int k = 0; k < 4; k++) cc[i][j][k] = 0.f;

#define DN_LOAD(b, k0)                                                  \
    do {                                                                \
        uint32_t o = sb + (b) * DN_BUF;                                 \
        load_tile128(o,         ap, INTER, (k0),      s0, s1, tid);     \
        load_tile128(o + 10240, ap, INTER, (k0) + 32, s0, s1, tid);     \
        load_tile128(o + 20480, bp, INTER, (k0),      16, 16, tid);     \
        load_tile128(o + 30720, bp, INTER, (k0) + 32, 16, 16, tid);     \
        CP_COMMIT();                                                    \
    } while (0)

    DN_LOAD(0, 0);
    const int KC = INTER / 64;  // 22 chunks
    for (int kc = 0; kc < KC; kc++) {
        CP_WAIT0();
        __syncthreads();
        if (kc + 1 < KC) DN_LOAD((kc + 1) & 1, (kc + 1) * 64);
        const uint32_t buf = sb + (kc & 1) * DN_BUF;

        uint32_t ha[2][8][2];
#pragma unroll
        for (int i = 0; i < 2; i++)
#pragma unroll
            for (int j = 0; j < 8; j++) { ha[i][j][0] = 0u; ha[i][j][1] = 0u; }
#pragma unroll
        for (int ks = 0; ks < 4; ks++) {
            const int sub = ks >> 1;
            const int k0  = (ks & 1) * 16;
            const uint32_t bufA = buf + sub * 10240;
            const uint32_t bufB = buf + 20480 + sub * 10240;
            uint32_t A0[4], A1[4];
            fragA(A0, bufA, wm * 32,      k0, lane);
            fragA(A1, bufA, wm * 32 + 16, k0, lane);
#pragma unroll
            for (int p = 0; p < 4; p++) {
                uint32_t Fb[4];
                fragB2(Fb, bufB, wn * 64 + p * 16, k0, lane);
                const int q = p * 2;
                MMAH(ha[0][q],   A0, Fb);
                MMAH(ha[1][q],   A1, Fb);
                MMAH(ha[0][q+1], A0, Fb + 2);
                MMAH(ha[1][q+1], A1, Fb + 2);
            }
        }
#pragma unroll
        for (int i = 0; i < 2; i++)
#pragma unroll
            for (int j = 0; j < 8; j++) spill(cc[i][j], ha[i][j]);
    }

    // epilogue: scale by probs, write fp32 out
#pragma unroll
    for (int mt = 0; mt < 2; mt++)
#pragma unroll
        for (int half = 0; half < 2; half++) {
            const int r = wm * 32 + mt * 16 + half * 8 + (lane >> 2);
            if (r < nrows) {
                const float p = probs[row0 + r];
                float* op = out + (size_t)(row0 + r) * HID + n0 + wn * 64;
#pragma unroll
                for (int nt = 0; nt < 8; nt++) {
                    const int col = nt * 8 + (lane & 3) * 2;
                    float2 v;
                    v.x = p * cc[mt][nt][half * 2];
                    v.y = p * cc[mt][nt][half * 2 + 1];
                    *(float2*)(op + col) = v;
                }
            }
        }
}

// ---------------------------------------------------------------------------
// Launch
// ---------------------------------------------------------------------------
extern "C" void kernel_launch(void* const* d_in, const int* in_sizes, int n_in,
                              void* d_out, int out_size) {
    const float* x     = (const float*)d_in[0];
    const float* probs = (const float*)d_in[1];
    const float* wg    = (const float*)d_in[2];
    const float* wu    = (const float*)d_in[3];
    const float* wd    = (const float*)d_in[4];
    const int*   tpe   = (const int*)d_in[5];
    float*       out   = (float*)d_out;

    cudaFuncSetAttribute(k_gateup, cudaFuncAttributeMaxDynamicSharedMemorySize, GU_SMEM);
    cudaFuncSetAttribute(k_down,   cudaFuncAttributeMaxDynamicSharedMemorySize, DN_SMEM);

    convert_x<<<2048, 256>>>(x, tpe);

    dim3 tb(16, 16);
    transpose_cvt_gu<<<dim3(HID / 32, INTER / 32, 2 * NE), tb>>>(wg, wu);
    transpose_cvt_d<<<dim3(INTER / 32, HID / 32, NE), tb>>>(wd);

    k_gateup<<<dim3(INTER / 64, MAXGRIDY), 256, GU_SMEM>>>();
    k_down<<<dim3(HID / 128, MAXGRIDY), 256, DN_SMEM>>>(probs, out);
}

// round 14
// speedup vs baseline: 1.3985x; 1.3985x over previous
#include <cuda_runtime.h>
#include <cuda_fp16.h>
#include <stdint.h>
#include <math.h>

#define NE 8
#define HID 2048
#define INTER 1408
#define TOT 8192
#define MAXTILES 96
#define MAXGRIDY 72

// ---------------------------------------------------------------------------
// Device globals (fp16 single plane everywhere)
// ---------------------------------------------------------------------------
__device__ int g_tile_expert[MAXTILES];
__device__ int g_tile_row0[MAXTILES];
__device__ int g_tile_nrows[MAXTILES];
__device__ int g_ntiles;

__device__ __half g_x[(size_t)TOT * HID];
// transposed weights: [E][N][K], K contiguous
__device__ __half g_wg[(size_t)NE * INTER * HID];
__device__ __half g_wu[(size_t)NE * INTER * HID];
__device__ __half g_wd[(size_t)NE * HID * INTER];
__device__ __half g_h[(size_t)TOT * INTER];

// ---------------------------------------------------------------------------
// Helpers (base-target PTX: mma.sync sm_80, cp.async sm_80, ldmatrix sm_75)
// ---------------------------------------------------------------------------
__device__ __forceinline__ uint32_t smem_u32(const void* p) {
    uint32_t a;
    asm("{ .reg .u64 t; cvta.to.shared.u64 t, %1; cvt.u32.u64 %0, t; }"
        : "=r"(a) : "l"(p));
    return a;
}

__device__ __forceinline__ void cp16(uint32_t dst, const void* src, int srcsize) {
    asm volatile("cp.async.cg.shared.global [%0], [%1], 16, %2;"
                 :: "r"(dst), "l"(src), "r"(srcsize));
}
#define CP_COMMIT() asm volatile("cp.async.commit_group;")
#define CP_WAIT0()  asm volatile("cp.async.wait_group 0;")

__device__ __forceinline__ void mma16816(float& c0, float& c1, float& c2, float& c3,
                                         const uint32_t a[4], const uint32_t* b) {
    asm volatile(
        "mma.sync.aligned.m16n8k16.row.col.f32.f16.f16.f32 "
        "{%0,%1,%2,%3},{%4,%5,%6,%7},{%8,%9},{%0,%1,%2,%3};"
        : "+f"(c0), "+f"(c1), "+f"(c2), "+f"(c3)
        : "r"(a[0]), "r"(a[1]), "r"(a[2]), "r"(a[3]), "r"(b[0]), "r"(b[1]));
}
#define MMA(C, A, B) mma16816((C)[0], (C)[1], (C)[2], (C)[3], A, B)

__device__ __forceinline__ void ldm_x4(uint32_t r[4], uint32_t addr) {
    asm volatile("ldmatrix.sync.aligned.m8n8.x4.shared.b16 {%0,%1,%2,%3}, [%4];"
                 : "=r"(r[0]), "=r"(r[1]), "=r"(r[2]), "=r"(r[3]) : "r"(addr));
}

// Row stride 80 B (conflict-free for cp.async stores and ldmatrix reads)
#define RSTR 80

// A fragment group (16 rows x 16 k): one ldmatrix.x4 -> mma operand order
__device__ __forceinline__ void fragA(uint32_t a[4], uint32_t tile, int rb, int k0, int lane) {
    uint32_t addr = tile + (uint32_t)(rb + (lane & 15)) * RSTR
                         + (uint32_t)(k0 + (lane >> 4) * 8) * 2;
    ldm_x4(a, addr);
}
// B fragment pair (two adjacent n-octets x 16 k from [n][k] tile)
__device__ __forceinline__ void fragB2(uint32_t b[4], uint32_t tile, int nb, int k0, int lane) {
    uint32_t addr = tile + (uint32_t)(nb + ((lane >> 4) * 8) + (lane & 7)) * RSTR
                         + (uint32_t)(k0 + ((lane >> 3) & 1) * 8) * 2;
    ldm_x4(b, addr);
}

// 128-row x 32-col fp16 tile via cp.async; per-thread sizes precomputed
__device__ __forceinline__ void load_tile128(uint32_t sdst, const __half* src,
                                             int ldk, int k0, int s0, int s1, int tid) {
    const int r = tid >> 2, c = tid & 3;
    cp16(sdst + r * RSTR + c * 16, src + (size_t)r * ldk + k0 + c * 8, s0);
    cp16(sdst + (r + 64) * RSTR + c * 16, src + (size_t)(r + 64) * ldk + k0 + c * 8, s1);
}
__device__ __forceinline__ void load_tile64(uint32_t sdst, const __half* src,
                                            int ldk, int k0, int tid) {
    const int r = tid >> 2, c = tid & 3;
    cp16(sdst + r * RSTR + c * 16, src + (size_t)r * ldk + k0 + c * 8, 16);
}

// ---------------------------------------------------------------------------
// Prep kernels
// ---------------------------------------------------------------------------
__global__ void convert_x(const float* __restrict__ x, const int* __restrict__ tpe) {
    if (blockIdx.x == 0 && threadIdx.x == 0) {
        int off = 0, nt = 0;
        for (int e = 0; e < NE; e++) {
            int n = tpe[e];
            for (int r = 0; r < n; r += 128) {
                g_tile_expert[nt] = e;
                g_tile_row0[nt]   = off + r;
                g_tile_nrows[nt]  = (n - r < 128) ? (n - r) : 128;
                nt++;
            }
            off += n;
        }
        g_ntiles = nt;
    }
    const size_t n4 = (size_t)TOT * HID / 4;
    for (size_t i = blockIdx.x * blockDim.x + threadIdx.x; i < n4;
         i += (size_t)gridDim.x * blockDim.x) {
        float4 v = ((const float4*)x)[i];
        __half2 p0 = __floats2half2_rn(v.x, v.y);
        __half2 p1 = __floats2half2_rn(v.z, v.w);
        ((uint2*)g_x)[i] = make_uint2(*(uint32_t*)&p0, *(uint32_t*)&p1);
    }
}

// z<NE: wg, z>=NE: wu.  [E][HID][INTER] fp32 -> [E][INTER][HID] fp16.
__global__ void transpose_cvt_gu(const float* __restrict__ wg,
                                 const float* __restrict__ wu) {
    __shared__ float t[32][33];
    const int z = blockIdx.z;
    const int e = z & (NE - 1);
    const bool isu = z >= NE;
    const float* src = (isu ? wu : wg) + (size_t)e * HID * INTER;
    __half* dst = (isu ? g_wu : g_wg) + (size_t)e * HID * INTER;
    const int k0 = blockIdx.x * 32, n0 = blockIdx.y * 32;
    const int tx = threadIdx.x, ty = threadIdx.y;
#pragma unroll
    for (int jj = 0; jj < 2; jj++) {
        const int kl = ty + jj * 16;
        float2 v = *(const float2*)(src + (size_t)(k0 + kl) * INTER + n0 + 2 * tx);
        t[kl][2 * tx] = v.x;
        t[kl][2 * tx + 1] = v.y;
    }
    __syncthreads();
#pragma unroll
    for (int jj = 0; jj < 2; jj++) {
        const int nl = ty + jj * 16;
        __half2 p = __floats2half2_rn(t[2 * tx][nl], t[2 * tx + 1][nl]);
        *(uint32_t*)(dst + (size_t)(n0 + nl) * HID + k0 + 2 * tx) = *(uint32_t*)&p;
    }
}

// [E][INTER][HID] fp32 -> [E][HID][INTER] fp16
__global__ void transpose_cvt_d(const float* __restrict__ wd) {
    __shared__ float t[32][33];
    const int e = blockIdx.z;
    const float* src = wd + (size_t)e * INTER * HID;
    __half* dst = g_wd + (size_t)e * INTER * HID;
    const int k0 = blockIdx.x * 32, n0 = blockIdx.y * 32;
    const int tx = threadIdx.x, ty = threadIdx.y;
#pragma unroll
    for (int jj = 0; jj < 2; jj++) {
        const int kl = ty + jj * 16;
        float2 v = *(const float2*)(src + (size_t)(k0 + kl) * HID + n0 + 2 * tx);
        t[kl][2 * tx] = v.x;
        t[kl][2 * tx + 1] = v.y;
    }
    __syncthreads();
#pragma unroll
    for (int jj = 0; jj < 2; jj++) {
        const int nl = ty + jj * 16;
        __half2 p = __floats2half2_rn(t[2 * tx][nl], t[2 * tx + 1][nl]);
        *(uint32_t*)(dst + (size_t)(n0 + nl) * INTER + k0 + 2 * tx) = *(uint32_t*)&p;
    }
}

// ---------------------------------------------------------------------------
// Fused gate+up grouped GEMM (fp16). CTA: M=128 x N=64 (per matrix), BK=64
// (two 32-k sub-tiles per stage). 8 warps (4M x 2N), warp 32x32 per matrix.
// 2-stage, 1 barrier per 64-k chunk.  [identical to measured-best R11]
// ---------------------------------------------------------------------------
#define GU_BUF 40960
#define GU_SMEM (2 * GU_BUF)

__global__ void __launch_bounds__(256, 2) k_gateup() {
    const int t = blockIdx.y;
    if (t >= g_ntiles) return;
    const int e     = __ldg(&g_tile_expert[t]);
    const int row0  = __ldg(&g_tile_row0[t]);
    const int nrows = __ldg(&g_tile_nrows[t]);
    const int n0    = blockIdx.x * 64;

    extern __shared__ char smem[];
    const uint32_t sb = smem_u32(smem);
    const int tid  = threadIdx.x;
    const int lane = tid & 31;
    const int wid  = tid >> 5;
    const int wm   = wid & 3;
    const int wn   = wid >> 2;
    const int s0 = ((tid >> 2) < nrows) ? 16 : 0;
    const int s1 = ((tid >> 2) + 64 < nrows) ? 16 : 0;

    const __half* xp = g_x + (size_t)row0 * HID;
    const size_t wbase = (size_t)e * INTER * HID + (size_t)n0 * HID;
    const __half* gp = g_wg + wbase;
    const __half* up = g_wu + wbase;

    float cg[2][4][4], cu[2][4][4];
#pragma unroll
    for (int i = 0; i < 2; i++)
#pragma unroll
        for (int j = 0; j < 4; j++)
#pragma unroll
            for (int k = 0; k < 4; k++) { cg[i][j][k] = 0.f; cu[i][j][k] = 0.f; }

#define GU_LOAD(b, k0)                                                  \
    do {                                                                \
        uint32_t o = sb + (b) * GU_BUF;                                 \
        load_tile128(o,         xp, HID, (k0),      s0, s1, tid);       \
        load_tile128(o + 10240, xp, HID, (k0) + 32, s0, s1, tid);       \
        load_tile64(o + 20480,  gp, HID, (k0),      tid);               \
        load_tile64(o + 25600,  gp, HID, (k0) + 32, tid);               \
        load_tile64(o + 30720,  up, HID, (k0),      tid);               \
        load_tile64(o + 35840,  up, HID, (k0) + 32, tid);               \
        CP_COMMIT();                                                    \
    } while (0)

    GU_LOAD(0, 0);
    const int KC = HID / 64;   // 32 chunks
    for (int kc = 0; kc < KC; kc++) {
        CP_WAIT0();
        __syncthreads();
        if (kc + 1 < KC) GU_LOAD((kc + 1) & 1, (kc + 1) * 64);
        const uint32_t buf = sb + (kc & 1) * GU_BUF;
#pragma unroll
        for (int ks = 0; ks < 4; ks++) {
            const int sub = ks >> 1;
            const int k0  = (ks & 1) * 16;
            const uint32_t bufA = buf + sub * 10240;
            const uint32_t bufG = buf + 20480 + sub * 5120;
            const uint32_t bufU = buf + 30720 + sub * 5120;
            uint32_t A0[4], A1[4];
            fragA(A0, bufA, wm * 32,      k0, lane);
            fragA(A1, bufA, wm * 32 + 16, k0, lane);
#pragma unroll
            for (int p = 0; p < 2; p++) {
                const int nb = wn * 32 + p * 16;
                uint32_t Bg[4], Bu[4];
                fragB2(Bg, bufG, nb, k0, lane);
                fragB2(Bu, bufU, nb, k0, lane);
                const int q = p * 2;
                MMA(cg[0][q],   A0, Bg);
                MMA(cg[1][q],   A1, Bg);
                MMA(cg[0][q+1], A0, Bg + 2);
                MMA(cg[1][q+1], A1, Bg + 2);
                MMA(cu[0][q],   A0, Bu);
                MMA(cu[1][q],   A1, Bu);
                MMA(cu[0][q+1], A0, Bu + 2);
                MMA(cu[1][q+1], A1, Bu + 2);
            }
        }
    }

    // epilogue: silu(gate)*up -> h (fp16)
#pragma unroll
    for (int mt = 0; mt < 2; mt++)
#pragma unroll
        for (int half = 0; half < 2; half++) {
            const int r = wm * 32 + mt * 16 + half * 8 + (lane >> 2);
            if (r < nrows) {
                __half* hp = g_h + (size_t)(row0 + r) * INTER + n0 + wn * 32;
#pragma unroll
                for (int nt = 0; nt < 4; nt++) {
                    const float gg0 = cg[mt][nt][half * 2], gg1 = cg[mt][nt][half * 2 + 1];
                    const float uu0 = cu[mt][nt][half * 2], uu1 = cu[mt][nt][half * 2 + 1];
                    const float h0 = uu0 * gg0 / (1.f + __expf(-gg0));
                    const float h1 = uu1 * gg1 / (1.f + __expf(-gg1));
                    __half2 p = __floats2half2_rn(h0, h1);
                    *(uint32_t*)(hp + nt * 8 + (lane & 3) * 2) = *(uint32_t*)&p;
                }
            }
        }
}

// ---------------------------------------------------------------------------
// Down grouped GEMM (fp16). CTA: M=128 x N=128, BK=64 (two 32-k sub-tiles).
// 8 warps (4 x 2), warp 32x64.  [identical to measured-best R11]
// ---------------------------------------------------------------------------
#define DN_BUF 40960
#define DN_SMEM (2 * DN_BUF)

__global__ void __launch_bounds__(256, 2) k_down(const float* __restrict__ probs,
                                                 float* __restrict__ out) {
    const int t = blockIdx.y;
    if (t >= g_ntiles) return;
    const int e     = __ldg(&g_tile_expert[t]);
    const int row0  = __ldg(&g_tile_row0[t]);
    const int nrows = __ldg(&g_tile_nrows[t]);
    const int n0    = blockIdx.x * 128;

    extern __shared__ char smem[];
    const uint32_t sb = smem_u32(smem);
    const int tid  = threadIdx.x;
    const int lane = tid & 31;
    const int wid  = tid >> 5;
    const int wm   = wid & 3;
    const int wn   = wid >> 2;
    const int s0 = ((tid >> 2) < nrows) ? 16 : 0;
    const int s1 = ((tid >> 2) + 64 < nrows) ? 16 : 0;

    const __half* ap = g_h + (size_t)row0 * INTER;
    const size_t wbase = (size_t)e * HID * INTER + (size_t)n0 * INTER;
    const __half* bp = g_wd + wbase;

    float cc[2][8][4];
#pragma unroll
    for (int i = 0; i < 2; i++)
#pragma unroll
        for (int j = 0; j < 8; j++)
#pragma unroll
            for (int k = 0; k < 4; k++) cc[i][j][k] = 0.f;

#define DN_LOAD(b, k0)                                                  \
    do {                                                                \
        uint32_t o = sb + (b) * DN_BUF;                                 \
        load_tile128(o,         ap, INTER, (k0),      s0, s1, tid);     \
        load_tile128(o + 10240, ap, INTER, (k0) + 32, s0, s1, tid);     \
        load_tile128(o + 20480, bp, INTER, (k0),      16, 16, tid);     \
        load_tile128(o + 30720, bp, INTER, (k0) + 32, 16, 16, tid);     \
        CP_COMMIT();                                                    \
    } while (0)

    DN_LOAD(0, 0);
    const int KC = INTER / 64;  // 22 chunks
    for (int kc = 0; kc < KC; kc++) {
        CP_WAIT0();
        __syncthreads();
        if (kc + 1 < KC) DN_LOAD((kc + 1) & 1, (kc + 1) * 64);
        const uint32_t buf = sb + (kc & 1) * DN_BUF;
#pragma unroll
        for (int ks = 0; ks < 4; ks++) {
            const int sub = ks >> 1;
            const int k0  = (ks & 1) * 16;
            const uint32_t bufA = buf + sub * 10240;
            const uint32_t bufB = buf + 20480 + sub * 10240;
            uint32_t A0[4], A1[4];
            fragA(A0, bufA, wm * 32,      k0, lane);
            fragA(A1, bufA, wm * 32 + 16, k0, lane);
#pragma unroll
            for (int p = 0; p < 4; p++) {
                const int nb = wn * 64 + p * 16;
                uint32_t Fb[4];
                fragB2(Fb, bufB, nb, k0, lane);
                const int q = p * 2;
                MMA(cc[0][q],   A0, Fb);
                MMA(cc[1][q],   A1, Fb);
                MMA(cc[0][q+1], A0, Fb + 2);
                MMA(cc[1][q+1], A1, Fb + 2);
            }
        }
    }

    // epilogue: scale by probs, write fp32 out
#pragma unroll
    for (int mt = 0; mt < 2; mt++)
#pragma unroll
        for (int half = 0; half < 2; half++) {
            const int r = wm * 32 + mt * 16 + half * 8 + (lane >> 2);
            if (r < nrows) {
                const float p = probs[row0 + r];
                float* op = out + (size_t)(row0 + r) * HID + n0 + wn * 64;
#pragma unroll
                for (int nt = 0; nt < 8; nt++) {
                    const int col = nt * 8 + (lane & 3) * 2;
                    float2 v;
                    v.x = p * cc[mt][nt][half * 2];
                    v.y = p * cc[mt][nt][half * 2 + 1];
                    *(float2*)(op + col) = v;
                }
            }
        }
}

// ---------------------------------------------------------------------------
// Launch: transpose_cvt_d forked onto a non-blocking stream so it overlaps
// k_gateup (which leaves ~75% of warp slots and ~94% of DRAM BW idle).
// Event fork-join keeps everything in one capturable dependency graph.
// ---------------------------------------------------------------------------
extern "C" void kernel_launch(void* const* d_in, const int* in_sizes, int n_in,
                              void* d_out, int out_size) {
    const float* x     = (const float*)d_in[0];
    const float* probs = (const float*)d_in[1];
    const float* wg    = (const float*)d_in[2];
    const float* wu    = (const float*)d_in[3];
    const float* wd    = (const float*)d_in[4];
    const int*   tpe   = (const int*)d_in[5];
    float*       out   = (float*)d_out;

    cudaFuncSetAttribute(k_gateup, cudaFuncAttributeMaxDynamicSharedMemorySize, GU_SMEM);
    cudaFuncSetAttribute(k_down,   cudaFuncAttributeMaxDynamicSharedMemorySize, DN_SMEM);

    cudaStream_t s2;
    cudaStreamCreateWithFlags(&s2, cudaStreamNonBlocking);
    cudaEvent_t eFork, eJoin;
    cudaEventCreateWithFlags(&eFork, cudaEventDisableTiming);
    cudaEventCreateWithFlags(&eJoin, cudaEventDisableTiming);

    dim3 tb(16, 16);
    convert_x<<<2048, 256>>>(x, tpe);
    transpose_cvt_gu<<<dim3(HID / 32, INTER / 32, 2 * NE), tb>>>(wg, wu);

    // fork: down-weight transpose runs concurrently with k_gateup
    cudaEventRecord(eFork, 0);
    cudaStreamWaitEvent(s2, eFork, 0);
    transpose_cvt_d<<<dim3(INTER / 32, HID / 32, NE), tb, 0, s2>>>(wd);
    cudaEventRecord(eJoin, s2);

    k_gateup<<<dim3(INTER / 64, MAXGRIDY), 256, GU_SMEM>>>();

    // join: k_down needs both g_h (stream 0) and g_wd (s2)
    cudaStreamWaitEvent(0, eJoin, 0);
    k_down<<<dim3(HID / 128, MAXGRIDY), 256, DN_SMEM>>>(probs, out);
}

// round 15
// speedup vs baseline: 1.4430x; 1.0319x over previous
#include <cuda_runtime.h>
#include <cuda_fp16.h>
#include <stdint.h>
#include <math.h>

#define NE 8
#define HID 2048
#define INTER 1408
#define TOT 8192
#define MAXTILES 96
#define MAXGRIDY 72

// ---------------------------------------------------------------------------
// Device globals (fp16 single plane everywhere)
// ---------------------------------------------------------------------------
__device__ int g_tile_expert[MAXTILES];
__device__ int g_tile_row0[MAXTILES];
__device__ int g_tile_nrows[MAXTILES];
__device__ int g_ntiles;

__device__ __half g_x[(size_t)TOT * HID];
// transposed weights: [E][N][K], K contiguous
__device__ __half g_wg[(size_t)NE * INTER * HID];
__device__ __half g_wu[(size_t)NE * INTER * HID];
__device__ __half g_wd[(size_t)NE * HID * INTER];
__device__ __half g_h[(size_t)TOT * INTER];

// ---------------------------------------------------------------------------
// Helpers (base-target PTX: mma.sync sm_80, cp.async sm_80, ldmatrix sm_75)
// ---------------------------------------------------------------------------
__device__ __forceinline__ uint32_t smem_u32(const void* p) {
    uint32_t a;
    asm("{ .reg .u64 t; cvta.to.shared.u64 t, %1; cvt.u32.u64 %0, t; }"
        : "=r"(a) : "l"(p));
    return a;
}

__device__ __forceinline__ void cp16(uint32_t dst, const void* src, int srcsize) {
    asm volatile("cp.async.cg.shared.global [%0], [%1], 16, %2;"
                 :: "r"(dst), "l"(src), "r"(srcsize));
}
#define CP_COMMIT() asm volatile("cp.async.commit_group;")
#define CP_WAIT0()  asm volatile("cp.async.wait_group 0;")

__device__ __forceinline__ void mma16816(float& c0, float& c1, float& c2, float& c3,
                                         const uint32_t a[4], const uint32_t* b) {
    asm volatile(
        "mma.sync.aligned.m16n8k16.row.col.f32.f16.f16.f32 "
        "{%0,%1,%2,%3},{%4,%5,%6,%7},{%8,%9},{%0,%1,%2,%3};"
        : "+f"(c0), "+f"(c1), "+f"(c2), "+f"(c3)
        : "r"(a[0]), "r"(a[1]), "r"(a[2]), "r"(a[3]), "r"(b[0]), "r"(b[1]));
}
#define MMA(C, A, B) mma16816((C)[0], (C)[1], (C)[2], (C)[3], A, B)

__device__ __forceinline__ void ldm_x4(uint32_t r[4], uint32_t addr) {
    asm volatile("ldmatrix.sync.aligned.m8n8.x4.shared.b16 {%0,%1,%2,%3}, [%4];"
                 : "=r"(r[0]), "=r"(r[1]), "=r"(r[2]), "=r"(r[3]) : "r"(addr));
}

// Row stride 80 B (conflict-free for cp.async stores and ldmatrix reads)
#define RSTR 80

// A fragment group (16 rows x 16 k): one ldmatrix.x4 -> mma operand order
__device__ __forceinline__ void fragA(uint32_t a[4], uint32_t tile, int rb, int k0, int lane) {
    uint32_t addr = tile + (uint32_t)(rb + (lane & 15)) * RSTR
                         + (uint32_t)(k0 + (lane >> 4) * 8) * 2;
    ldm_x4(a, addr);
}
// B fragment pair (two adjacent n-octets x 16 k from [n][k] tile)
__device__ __forceinline__ void fragB2(uint32_t b[4], uint32_t tile, int nb, int k0, int lane) {
    uint32_t addr = tile + (uint32_t)(nb + ((lane >> 4) * 8) + (lane & 7)) * RSTR
                         + (uint32_t)(k0 + ((lane >> 3) & 1) * 8) * 2;
    ldm_x4(b, addr);
}

// 128-row x 32-col fp16 tile via cp.async; per-thread sizes precomputed
__device__ __forceinline__ void load_tile128(uint32_t sdst, const __half* src,
                                             int ldk, int k0, int s0, int s1, int tid) {
    const int r = tid >> 2, c = tid & 3;
    cp16(sdst + r * RSTR + c * 16, src + (size_t)r * ldk + k0 + c * 8, s0);
    cp16(sdst + (r + 64) * RSTR + c * 16, src + (size_t)(r + 64) * ldk + k0 + c * 8, s1);
}
__device__ __forceinline__ void load_tile64(uint32_t sdst, const __half* src,
                                            int ldk, int k0, int tid) {
    const int r = tid >> 2, c = tid & 3;
    cp16(sdst + r * RSTR + c * 16, src + (size_t)r * ldk + k0 + c * 8, 16);
}

// ---------------------------------------------------------------------------
// Prep kernels
// ---------------------------------------------------------------------------
__global__ void convert_x(const float* __restrict__ x, const int* __restrict__ tpe) {
    if (blockIdx.x == 0 && threadIdx.x == 0) {
        int off = 0, nt = 0;
        for (int e = 0; e < NE; e++) {
            int n = tpe[e];
            for (int r = 0; r < n; r += 128) {
                g_tile_expert[nt] = e;
                g_tile_row0[nt]   = off + r;
                g_tile_nrows[nt]  = (n - r < 128) ? (n - r) : 128;
                nt++;
            }
            off += n;
        }
        g_ntiles = nt;
    }
    const size_t n4 = (size_t)TOT * HID / 4;
    for (size_t i = blockIdx.x * blockDim.x + threadIdx.x; i < n4;
         i += (size_t)gridDim.x * blockDim.x) {
        float4 v = ((const float4*)x)[i];
        __half2 p0 = __floats2half2_rn(v.x, v.y);
        __half2 p1 = __floats2half2_rn(v.z, v.w);
        ((uint2*)g_x)[i] = make_uint2(*(uint32_t*)&p0, *(uint32_t*)&p1);
    }
}

// Transpose+convert, 64k x 32n tile per block, 128 B coalesced on BOTH sides.
// src [K][N] fp32 (n contiguous) -> dst [N][K] fp16 (k contiguous)
__device__ __forceinline__ void tc64(const float* __restrict__ src,
                                     __half* __restrict__ dst,
                                     int K, int N, int k0, int n0) {
    __shared__ float t[64][33];
    const int tx = threadIdx.x, ty = threadIdx.y;
#pragma unroll
    for (int jj = 0; jj < 4; jj++) {
        const int kl = ty + jj * 16;
        float2 v = *(const float2*)(src + (size_t)(k0 + kl) * N + n0 + 2 * tx);
        t[kl][2 * tx] = v.x;
        t[kl][2 * tx + 1] = v.y;
    }
    __syncthreads();
#pragma unroll
    for (int jj = 0; jj < 2; jj++) {
        const int nl = ty + jj * 16;
        __half2 p0 = __floats2half2_rn(t[4 * tx][nl],     t[4 * tx + 1][nl]);
        __half2 p1 = __floats2half2_rn(t[4 * tx + 2][nl], t[4 * tx + 3][nl]);
        *(uint2*)(dst + (size_t)(n0 + nl) * K + k0 + 4 * tx) =
            make_uint2(*(uint32_t*)&p0, *(uint32_t*)&p1);
    }
}

// z<NE: wg, z>=NE: wu.  [E][HID][INTER] fp32 -> [E][INTER][HID] fp16.
__global__ void transpose_cvt_gu(const float* __restrict__ wg,
                                 const float* __restrict__ wu) {
    const int z = blockIdx.z;
    const int e = z & (NE - 1);
    const bool isu = z >= NE;
    const float* src = (isu ? wu : wg) + (size_t)e * HID * INTER;
    __half* dst = (isu ? g_wu : g_wg) + (size_t)e * HID * INTER;
    tc64(src, dst, HID, INTER, blockIdx.x * 64, blockIdx.y * 32);
}

// [E][INTER][HID] fp32 -> [E][HID][INTER] fp16
__global__ void transpose_cvt_d(const float* __restrict__ wd) {
    const int e = blockIdx.z;
    const float* src = wd + (size_t)e * INTER * HID;
    __half* dst = g_wd + (size_t)e * INTER * HID;
    tc64(src, dst, INTER, HID, blockIdx.x * 64, blockIdx.y * 32);
}

// ---------------------------------------------------------------------------
// Fused gate+up grouped GEMM (fp16). CTA: M=128 x N=64 (per matrix), BK=64
// (two 32-k sub-tiles per stage). 8 warps (4M x 2N), warp 32x32 per matrix.
// 2-stage, 1 barrier per 64-k chunk.  [identical to measured-best R11/R14]
// ---------------------------------------------------------------------------
#define GU_BUF 40960
#define GU_SMEM (2 * GU_BUF)

__global__ void __launch_bounds__(256, 2) k_gateup() {
    const int t = blockIdx.y;
    if (t >= g_ntiles) return;
    const int e     = __ldg(&g_tile_expert[t]);
    const int row0  = __ldg(&g_tile_row0[t]);
    const int nrows = __ldg(&g_tile_nrows[t]);
    const int n0    = blockIdx.x * 64;

    extern __shared__ char smem[];
    const uint32_t sb = smem_u32(smem);
    const int tid  = threadIdx.x;
    const int lane = tid & 31;
    const int wid  = tid >> 5;
    const int wm   = wid & 3;
    const int wn   = wid >> 2;
    const int s0 = ((tid >> 2) < nrows) ? 16 : 0;
    const int s1 = ((tid >> 2) + 64 < nrows) ? 16 : 0;

    const __half* xp = g_x + (size_t)row0 * HID;
    const size_t wbase = (size_t)e * INTER * HID + (size_t)n0 * HID;
    const __half* gp = g_wg + wbase;
    const __half* up = g_wu + wbase;

    float cg[2][4][4], cu[2][4][4];
#pragma unroll
    for (int i = 0; i < 2; i++)
#pragma unroll
        for (int j = 0; j < 4; j++)
#pragma unroll
            for (int k = 0; k < 4; k++) { cg[i][j][k] = 0.f; cu[i][j][k] = 0.f; }

#define GU_LOAD(b, k0)                                                  \
    do {                                                                \
        uint32_t o = sb + (b) * GU_BUF;                                 \
        load_tile128(o,         xp, HID, (k0),      s0, s1, tid);       \
        load_tile128(o + 10240, xp, HID, (k0) + 32, s0, s1, tid);       \
        load_tile64(o + 20480,  gp, HID, (k0),      tid);               \
        load_tile64(o + 25600,  gp, HID, (k0) + 32, tid);               \
        load_tile64(o + 30720,  up, HID, (k0),      tid);               \
        load_tile64(o + 35840,  up, HID, (k0) + 32, tid);               \
        CP_COMMIT();                                                    \
    } while (0)

    GU_LOAD(0, 0);
    const int KC = HID / 64;   // 32 chunks
    for (int kc = 0; kc < KC; kc++) {
        CP_WAIT0();
        __syncthreads();
        if (kc + 1 < KC) GU_LOAD((kc + 1) & 1, (kc + 1) * 64);
        const uint32_t buf = sb + (kc & 1) * GU_BUF;
#pragma unroll
        for (int ks = 0; ks < 4; ks++) {
            const int sub = ks >> 1;
            const int k0  = (ks & 1) * 16;
            const uint32_t bufA = buf + sub * 10240;
            const uint32_t bufG = buf + 20480 + sub * 5120;
            const uint32_t bufU = buf + 30720 + sub * 5120;
            uint32_t A0[4], A1[4];
            fragA(A0, bufA, wm * 32,      k0, lane);
            fragA(A1, bufA, wm * 32 + 16, k0, lane);
#pragma unroll
            for (int p = 0; p < 2; p++) {
                const int nb = wn * 32 + p * 16;
                uint32_t Bg[4], Bu[4];
                fragB2(Bg, bufG, nb, k0, lane);
                fragB2(Bu, bufU, nb, k0, lane);
                const int q = p * 2;
                MMA(cg[0][q],   A0, Bg);
                MMA(cg[1][q],   A1, Bg);
                MMA(cg[0][q+1], A0, Bg + 2);
                MMA(cg[1][q+1], A1, Bg + 2);
                MMA(cu[0][q],   A0, Bu);
                MMA(cu[1][q],   A1, Bu);
                MMA(cu[0][q+1], A0, Bu + 2);
                MMA(cu[1][q+1], A1, Bu + 2);
            }
        }
    }

    // epilogue: silu(gate)*up -> h (fp16)
#pragma unroll
    for (int mt = 0; mt < 2; mt++)
#pragma unroll
        for (int half = 0; half < 2; half++) {
            const int r = wm * 32 + mt * 16 + half * 8 + (lane >> 2);
            if (r < nrows) {
                __half* hp = g_h + (size_t)(row0 + r) * INTER + n0 + wn * 32;
#pragma unroll
                for (int nt = 0; nt < 4; nt++) {
                    const float gg0 = cg[mt][nt][half * 2], gg1 = cg[mt][nt][half * 2 + 1];
                    const float uu0 = cu[mt][nt][half * 2], uu1 = cu[mt][nt][half * 2 + 1];
                    const float h0 = uu0 * gg0 / (1.f + __expf(-gg0));
                    const float h1 = uu1 * gg1 / (1.f + __expf(-gg1));
                    __half2 p = __floats2half2_rn(h0, h1);
                    *(uint32_t*)(hp + nt * 8 + (lane & 3) * 2) = *(uint32_t*)&p;
                }
            }
        }
}

// ---------------------------------------------------------------------------
// Down grouped GEMM (fp16). CTA: M=128 x N=128, BK=64 (two 32-k sub-tiles).
// 8 warps (4 x 2), warp 32x64.  [identical to measured-best R11/R14]
// ---------------------------------------------------------------------------
#define DN_BUF 40960
#define DN_SMEM (2 * DN_BUF)

__global__ void __launch_bounds__(256, 2) k_down(const float* __restrict__ probs,
                                                 float* __restrict__ out) {
    const int t = blockIdx.y;
    if (t >= g_ntiles) return;
    const int e     = __ldg(&g_tile_expert[t]);
    const int row0  = __ldg(&g_tile_row0[t]);
    const int nrows = __ldg(&g_tile_nrows[t]);
    const int n0    = blockIdx.x * 128;

    extern __shared__ char smem[];
    const uint32_t sb = smem_u32(smem);
    const int tid  = threadIdx.x;
    const int lane = tid & 31;
    const int wid  = tid >> 5;
    const int wm   = wid & 3;
    const int wn   = wid >> 2;
    const int s0 = ((tid >> 2) < nrows) ? 16 : 0;
    const int s1 = ((tid >> 2) + 64 < nrows) ? 16 : 0;

    const __half* ap = g_h + (size_t)row0 * INTER;
    const size_t wbase = (size_t)e * HID * INTER + (size_t)n0 * INTER;
    const __half* bp = g_wd + wbase;

    float cc[2][8][4];
#pragma unroll
    for (int i = 0; i < 2; i++)
#pragma unroll
        for (int j = 0; j < 8; j++)
#pragma unroll
            for (int k = 0; k < 4; k++) cc[i][j][k] = 0.f;

#define DN_LOAD(b, k0)                                                  \
    do {                                                                \
        uint32_t o = sb + (b) * DN_BUF;                                 \
        load_tile128(o,         ap, INTER, (k0),      s0, s1, tid);     \
        load_tile128(o + 10240, ap, INTER, (k0) + 32, s0, s1, tid);     \
        load_tile128(o + 20480, bp, INTER, (k0),      16, 16, tid);     \
        load_tile128(o + 30720, bp, INTER, (k0) + 32, 16, 16, tid);     \
        CP_COMMIT();                                                    \
    } while (0)

    DN_LOAD(0, 0);
    const int KC = INTER / 64;  // 22 chunks
    for (int kc = 0; kc < KC; kc++) {
        CP_WAIT0();
        __syncthreads();
        if (kc + 1 < KC) DN_LOAD((kc + 1) & 1, (kc + 1) * 64);
        const uint32_t buf = sb + (kc & 1) * DN_BUF;
#pragma unroll
        for (int ks = 0; ks < 4; ks++) {
            const int sub = ks >> 1;
            const int k0  = (ks & 1) * 16;
            const uint32_t bufA = buf + sub * 10240;
            const uint32_t bufB = buf + 20480 + sub * 10240;
            uint32_t A0[4], A1[4];
            fragA(A0, bufA, wm * 32,      k0, lane);
            fragA(A1, bufA, wm * 32 + 16, k0, lane);
#pragma unroll
            for (int p = 0; p < 4; p++) {
                const int nb = wn * 64 + p * 16;
                uint32_t Fb[4];
                fragB2(Fb, bufB, nb, k0, lane);
                const int q = p * 2;
                MMA(cc[0][q],   A0, Fb);
                MMA(cc[1][q],   A1, Fb);
                MMA(cc[0][q+1], A0, Fb + 2);
                MMA(cc[1][q+1], A1, Fb + 2);
            }
        }
    }

    // epilogue: scale by probs, write fp32 out
#pragma unroll
    for (int mt = 0; mt < 2; mt++)
#pragma unroll
        for (int half = 0; half < 2; half++) {
            const int r = wm * 32 + mt * 16 + half * 8 + (lane >> 2);
            if (r < nrows) {
                const float p = probs[row0 + r];
                float* op = out + (size_t)(row0 + r) * HID + n0 + wn * 64;
#pragma unroll
                for (int nt = 0; nt < 8; nt++) {
                    const int col = nt * 8 + (lane & 3) * 2;
                    float2 v;
                    v.x = p * cc[mt][nt][half * 2];
                    v.y = p * cc[mt][nt][half * 2 + 1];
                    *(float2*)(op + col) = v;
                }
            }
        }
}

// ---------------------------------------------------------------------------
// Launch. Dependency graph:
//   s0: transpose_cvt_gu ─┐
//   s2: convert_x ────────┼→ k_gateup ──→ k_down
//       └ transpose_cvt_d ┴──────────────↗ (overlaps k_gateup)
// ---------------------------------------------------------------------------
extern "C" void kernel_launch(void* const* d_in, const int* in_sizes, int n_in,
                              void* d_out, int out_size) {
    const float* x     = (const float*)d_in[0];
    const float* probs = (const float*)d_in[1];
    const float* wg    = (const float*)d_in[2];
    const float* wu    = (const float*)d_in[3];
    const float* wd    = (const float*)d_in[4];
    const int*   tpe   = (const int*)d_in[5];
    float*       out   = (float*)d_out;

    cudaFuncSetAttribute(k_gateup, cudaFuncAttributeMaxDynamicSharedMemorySize, GU_SMEM);
    cudaFuncSetAttribute(k_down,   cudaFuncAttributeMaxDynamicSharedMemorySize, DN_SMEM);

    cudaStream_t s2;
    cudaStreamCreateWithFlags(&s2, cudaStreamNonBlocking);
    cudaEvent_t eFork, eX, eD;
    cudaEventCreateWithFlags(&eFork, cudaEventDisableTiming);
    cudaEventCreateWithFlags(&eX,    cudaEventDisableTiming);
    cudaEventCreateWithFlags(&eD,    cudaEventDisableTiming);

    dim3 tb(16, 16);

    // fork side stream from capture origin
    cudaEventRecord(eFork, 0);
    cudaStreamWaitEvent(s2, eFork, 0);

    // s2: x conversion (+ tile table), then down-weight transpose (overlaps gateup)
    convert_x<<<1024, 256, 0, s2>>>(x, tpe);
    cudaEventRecord(eX, s2);
    transpose_cvt_d<<<dim3(INTER / 64, HID / 32, NE), tb, 0, s2>>>(wd);
    cudaEventRecord(eD, s2);

    // s0: gate/up weight transpose runs concurrently with convert_x
    transpose_cvt_gu<<<dim3(HID / 64, INTER / 32, 2 * NE), tb>>>(wg, wu);

    // gateup needs g_x (eX) and g_wg/g_wu (s0 order)
    cudaStreamWaitEvent(0, eX, 0);
    k_gateup<<<dim3(INTER / 64, MAXGRIDY), 256, GU_SMEM>>>();

    // down needs g_h (s0) and g_wd (eD)
    cudaStreamWaitEvent(0, eD, 0);
    k_down<<<dim3(HID / 128, MAXGRIDY), 256, DN_SMEM>>>(probs, out);
}

// round 17
// speedup vs baseline: 1.4528x; 1.0068x over previous
#include <cuda_runtime.h>
#include <cuda_fp16.h>
#include <stdint.h>
#include <math.h>

#define NE 8
#define HID 2048
#define INTER 1408
#define TOT 8192
#define MAXTILES 96
#define MAXGRIDY 72
#define NHALF (INTER / 2)   // 704

// ---------------------------------------------------------------------------
// Device globals (fp16 single plane everywhere)
// ---------------------------------------------------------------------------
__device__ int g_tile_expert[MAXTILES];
__device__ int g_tile_row0[MAXTILES];
__device__ int g_tile_nrows[MAXTILES];
__device__ int g_ntiles;

__device__ __half g_x[(size_t)TOT * HID];
// transposed weights: [E][N][K], K contiguous
__device__ __half g_wg[(size_t)NE * INTER * HID];
__device__ __half g_wu[(size_t)NE * INTER * HID];
__device__ __half g_wd[(size_t)NE * HID * INTER];
__device__ __half g_h[(size_t)TOT * INTER];

// ---------------------------------------------------------------------------
// Helpers (base-target PTX: mma.sync sm_80, cp.async sm_80, ldmatrix sm_75)
// ---------------------------------------------------------------------------
__device__ __forceinline__ uint32_t smem_u32(const void* p) {
    uint32_t a;
    asm("{ .reg .u64 t; cvta.to.shared.u64 t, %1; cvt.u32.u64 %0, t; }"
        : "=r"(a) : "l"(p));
    return a;
}

__device__ __forceinline__ void cp16(uint32_t dst, const void* src, int srcsize) {
    asm volatile("cp.async.cg.shared.global [%0], [%1], 16, %2;"
                 :: "r"(dst), "l"(src), "r"(srcsize));
}
#define CP_COMMIT() asm volatile("cp.async.commit_group;")
#define CP_WAIT0()  asm volatile("cp.async.wait_group 0;")

__device__ __forceinline__ void mma16816(float& c0, float& c1, float& c2, float& c3,
                                         const uint32_t a[4], const uint32_t* b) {
    asm volatile(
        "mma.sync.aligned.m16n8k16.row.col.f32.f16.f16.f32 "
        "{%0,%1,%2,%3},{%4,%5,%6,%7},{%8,%9},{%0,%1,%2,%3};"
        : "+f"(c0), "+f"(c1), "+f"(c2), "+f"(c3)
        : "r"(a[0]), "r"(a[1]), "r"(a[2]), "r"(a[3]), "r"(b[0]), "r"(b[1]));
}
#define MMA(C, A, B) mma16816((C)[0], (C)[1], (C)[2], (C)[3], A, B)

__device__ __forceinline__ void ldm_x4(uint32_t r[4], uint32_t addr) {
    asm volatile("ldmatrix.sync.aligned.m8n8.x4.shared.b16 {%0,%1,%2,%3}, [%4];"
                 : "=r"(r[0]), "=r"(r[1]), "=r"(r[2]), "=r"(r[3]) : "r"(addr));
}

// Row stride 80 B (conflict-free for cp.async stores and ldmatrix reads)
#define RSTR 80

// A fragment group (16 rows x 16 k): one ldmatrix.x4 -> mma operand order
__device__ __forceinline__ void fragA(uint32_t a[4], uint32_t tile, int rb, int k0, int lane) {
    uint32_t addr = tile + (uint32_t)(rb + (lane & 15)) * RSTR
                         + (uint32_t)(k0 + (lane >> 4) * 8) * 2;
    ldm_x4(a, addr);
}
// B fragment pair (two adjacent n-octets x 16 k from [n][k] tile)
__device__ __forceinline__ void fragB2(uint32_t b[4], uint32_t tile, int nb, int k0, int lane) {
    uint32_t addr = tile + (uint32_t)(nb + ((lane >> 4) * 8) + (lane & 7)) * RSTR
                         + (uint32_t)(k0 + ((lane >> 3) & 1) * 8) * 2;
    ldm_x4(b, addr);
}

// 128-row x 32-col fp16 tile via cp.async; per-thread sizes precomputed
__device__ __forceinline__ void load_tile128(uint32_t sdst, const __half* src,
                                             int ldk, int k0, int s0, int s1, int tid) {
    const int r = tid >> 2, c = tid & 3;
    cp16(sdst + r * RSTR + c * 16, src + (size_t)r * ldk + k0 + c * 8, s0);
    cp16(sdst + (r + 64) * RSTR + c * 16, src + (size_t)(r + 64) * ldk + k0 + c * 8, s1);
}
__device__ __forceinline__ void load_tile64(uint32_t sdst, const __half* src,
                                            int ldk, int k0, int tid) {
    const int r = tid >> 2, c = tid & 3;
    cp16(sdst + r * RSTR + c * 16, src + (size_t)r * ldk + k0 + c * 8, 16);
}

// ---------------------------------------------------------------------------
// Prep kernels
// ---------------------------------------------------------------------------
__global__ void convert_x(const float* __restrict__ x, const int* __restrict__ tpe) {
    if (blockIdx.x == 0 && threadIdx.x == 0) {
        int off = 0, nt = 0;
        for (int e = 0; e < NE; e++) {
            int n = tpe[e];
            for (int r = 0; r < n; r += 128) {
                g_tile_expert[nt] = e;
                g_tile_row0[nt]   = off + r;
                g_tile_nrows[nt]  = (n - r < 128) ? (n - r) : 128;
                nt++;
            }
            off += n;
        }
        g_ntiles = nt;
    }
    const size_t n4 = (size_t)TOT * HID / 4;
    for (size_t i = blockIdx.x * blockDim.x + threadIdx.x; i < n4;
         i += (size_t)gridDim.x * blockDim.x) {
        float4 v = ((const float4*)x)[i];
        __half2 p0 = __floats2half2_rn(v.x, v.y);
        __half2 p1 = __floats2half2_rn(v.z, v.w);
        ((uint2*)g_x)[i] = make_uint2(*(uint32_t*)&p0, *(uint32_t*)&p1);
    }
}

// Transpose+convert, 64k x 32n tile per block, 128 B coalesced on BOTH sides.
__device__ __forceinline__ void tc64(const float* __restrict__ src,
                                     __half* __restrict__ dst,
                                     int K, int N, int k0, int n0) {
    __shared__ float t[64][33];
    const int tx = threadIdx.x, ty = threadIdx.y;
#pragma unroll
    for (int jj = 0; jj < 4; jj++) {
        const int kl = ty + jj * 16;
        float2 v = *(const float2*)(src + (size_t)(k0 + kl) * N + n0 + 2 * tx);
        t[kl][2 * tx] = v.x;
        t[kl][2 * tx + 1] = v.y;
    }
    __syncthreads();
#pragma unroll
    for (int jj = 0; jj < 2; jj++) {
        const int nl = ty + jj * 16;
        __half2 p0 = __floats2half2_rn(t[4 * tx][nl],     t[4 * tx + 1][nl]);
        __half2 p1 = __floats2half2_rn(t[4 * tx + 2][nl], t[4 * tx + 3][nl]);
        *(uint2*)(dst + (size_t)(n0 + nl) * K + k0 + 4 * tx) =
            make_uint2(*(uint32_t*)&p0, *(uint32_t*)&p1);
    }
}

// z<NE: wg, z>=NE: wu.  Covers n in [n_base, n_base + NHALF).
__global__ void transpose_cvt_gu(const float* __restrict__ wg,
                                 const float* __restrict__ wu, int n_base) {
    const int z = blockIdx.z;
    const int e = z & (NE - 1);
    const bool isu = z >= NE;
    const float* src = (isu ? wu : wg) + (size_t)e * HID * INTER;
    __half* dst = (isu ? g_wu : g_wg) + (size_t)e * HID * INTER;
    tc64(src, dst, HID, INTER, blockIdx.x * 64, n_base + blockIdx.y * 32);
}

// [E][INTER][HID] fp32 -> [E][HID][INTER] fp16
__global__ void transpose_cvt_d(const float* __restrict__ wd) {
    const int e = blockIdx.z;
    const float* src = wd + (size_t)e * INTER * HID;
    __half* dst = g_wd + (size_t)e * INTER * HID;
    tc64(src, dst, INTER, HID, blockIdx.x * 64, blockIdx.y * 32);
}

// ---------------------------------------------------------------------------
// Fused gate+up grouped GEMM (fp16). CTA: M=128 x N=64 (per matrix), BK=64.
// n_base selects which INTER half this launch covers.
// [GEMM body identical to measured-best R11/R15]
// ---------------------------------------------------------------------------
#define GU_BUF 40960
#define GU_SMEM (2 * GU_BUF)

__global__ void __launch_bounds__(256, 2) k_gateup(int n_base) {
    const int t = blockIdx.y;
    if (t >= g_ntiles) return;
    const int e     = __ldg(&g_tile_expert[t]);
    const int row0  = __ldg(&g_tile_row0[t]);
    const int nrows = __ldg(&g_tile_nrows[t]);
    const int n0    = n_base + blockIdx.x * 64;

    extern __shared__ char smem[];
    const uint32_t sb = smem_u32(smem);
    const int tid  = threadIdx.x;
    const int lane = tid & 31;
    const int wid  = tid >> 5;
    const int wm   = wid & 3;
    const int wn   = wid >> 2;
    const int s0 = ((tid >> 2) < nrows) ? 16 : 0;
    const int s1 = ((tid >> 2) + 64 < nrows) ? 16 : 0;

    const __half* xp = g_x + (size_t)row0 * HID;
    const size_t wbase = (size_t)e * INTER * HID + (size_t)n0 * HID;
    const __half* gp = g_wg + wbase;
    const __half* up = g_wu + wbase;

    float cg[2][4][4], cu[2][4][4];
#pragma unroll
    for (int i = 0; i < 2; i++)
#pragma unroll
        for (int j = 0; j < 4; j++)
#pragma unroll
            for (int k = 0; k < 4; k++) { cg[i][j][k] = 0.f; cu[i][j][k] = 0.f; }

#define GU_LOAD(b, k0)                                                  \
    do {                                                                \
        uint32_t o = sb + (b) * GU_BUF;                                 \
        load_tile128(o,         xp, HID, (k0),      s0, s1, tid);       \
        load_tile128(o + 10240, xp, HID, (k0) + 32, s0, s1, tid);       \
        load_tile64(o + 20480,  gp, HID, (k0),      tid);               \
        load_tile64(o + 25600,  gp, HID, (k0) + 32, tid);               \
        load_tile64(o + 30720,  up, HID, (k0),      tid);               \
        load_tile64(o + 35840,  up, HID, (k0) + 32, tid);               \
        CP_COMMIT();                                                    \
    } while (0)

    GU_LOAD(0, 0);
    const int KC = HID / 64;   // 32 chunks
    for (int kc = 0; kc < KC; kc++) {
        CP_WAIT0();
        __syncthreads();
        if (kc + 1 < KC) GU_LOAD((kc + 1) & 1, (kc + 1) * 64);
        const uint32_t buf = sb + (kc & 1) * GU_BUF;
#pragma unroll
        for (int ks = 0; ks < 4; ks++) {
            const int sub = ks >> 1;
            const int k0  = (ks & 1) * 16;
            const uint32_t bufA = buf + sub * 10240;
            const uint32_t bufG = buf + 20480 + sub * 5120;
            const uint32_t bufU = buf + 30720 + sub * 5120;
            uint32_t A0[4], A1[4];
            fragA(A0, bufA, wm * 32,      k0, lane);
            fragA(A1, bufA, wm * 32 + 16, k0, lane);
#pragma unroll
            for (int p = 0; p < 2; p++) {
                const int nb = wn * 32 + p * 16;
                uint32_t Bg[4], Bu[4];
                fragB2(Bg, bufG, nb, k0, lane);
                fragB2(Bu, bufU, nb, k0, lane);
                const int q = p * 2;
                MMA(cg[0][q],   A0, Bg);
                MMA(cg[1][q],   A1, Bg);
                MMA(cg[0][q+1], A0, Bg + 2);
                MMA(cg[1][q+1], A1, Bg + 2);
                MMA(cu[0][q],   A0, Bu);
                MMA(cu[1][q],   A1, Bu);
                MMA(cu[0][q+1], A0, Bu + 2);
                MMA(cu[1][q+1], A1, Bu + 2);
            }
        }
    }

    // epilogue: silu(gate)*up -> h (fp16)
#pragma unroll
    for (int mt = 0; mt < 2; mt++)
#pragma unroll
        for (int half = 0; half < 2; half++) {
            const int r = wm * 32 + mt * 16 + half * 8 + (lane >> 2);
            if (r < nrows) {
                __half* hp = g_h + (size_t)(row0 + r) * INTER + n0 + wn * 32;
#pragma unroll
                for (int nt = 0; nt < 4; nt++) {
                    const float gg0 = cg[mt][nt][half * 2], gg1 = cg[mt][nt][half * 2 + 1];
                    const float uu0 = cu[mt][nt][half * 2], uu1 = cu[mt][nt][half * 2 + 1];
                    const float h0 = uu0 * gg0 / (1.f + __expf(-gg0));
                    const float h1 = uu1 * gg1 / (1.f + __expf(-gg1));
                    __half2 p = __floats2half2_rn(h0, h1);
                    *(uint32_t*)(hp + nt * 8 + (lane & 3) * 2) = *(uint32_t*)&p;
                }
            }
        }
}

// ---------------------------------------------------------------------------
// Down grouped GEMM (fp16). CTA: M=128 x N=128, BK=64. [identical to R11/R15]
// ---------------------------------------------------------------------------
#define DN_BUF 40960
#define DN_SMEM (2 * DN_BUF)

__global__ void __launch_bounds__(256, 2) k_down(const float* __restrict__ probs,
                                                 float* __restrict__ out) {
    const int t = blockIdx.y;
    if (t >= g_ntiles) return;
    const int e     = __ldg(&g_tile_expert[t]);
    const int row0  = __ldg(&g_tile_row0[t]);
    const int nrows = __ldg(&g_tile_nrows[t]);
    const int n0    = blockIdx.x * 128;

    extern __shared__ char smem[];
    const uint32_t sb = smem_u32(smem);
    const int tid  = threadIdx.x;
    const int lane = tid & 31;
    const int wid  = tid >> 5;
    const int wm   = wid & 3;
    const int wn   = wid >> 2;
    const int s0 = ((tid >> 2) < nrows) ? 16 : 0;
    const int s1 = ((tid >> 2) + 64 < nrows) ? 16 : 0;

    const __half* ap = g_h + (size_t)row0 * INTER;
    const size_t wbase = (size_t)e * HID * INTER + (size_t)n0 * INTER;
    const __half* bp = g_wd + wbase;

    float cc[2][8][4];
#pragma unroll
    for (int i = 0; i < 2; i++)
#pragma unroll
        for (int j = 0; j < 8; j++)
#pragma unroll
            for (int k = 0; k < 4; k++) cc[i][j][k] = 0.f;

#define DN_LOAD(b, k0)                                                  \
    do {                                                                \
        uint32_t o = sb + (b) * DN_BUF;                                 \
        load_tile128(o,         ap, INTER, (k0),      s0, s1, tid);     \
        load_tile128(o + 10240, ap, INTER, (k0) + 32, s0, s1, tid);     \
        load_tile128(o + 20480, bp, INTER, (k0),      16, 16, tid);     \
        load_tile128(o + 30720, bp, INTER, (k0) + 32, 16, 16, tid);     \
        CP_COMMIT();                                                    \
    } while (0)

    DN_LOAD(0, 0);
    const int KC = INTER / 64;  // 22 chunks
    for (int kc = 0; kc < KC; kc++) {
        CP_WAIT0();
        __syncthreads();
        if (kc + 1 < KC) DN_LOAD((kc + 1) & 1, (kc + 1) * 64);
        const uint32_t buf = sb + (kc & 1) * DN_BUF;
#pragma unroll
        for (int ks = 0; ks < 4; ks++) {
            const int sub = ks >> 1;
            const int k0  = (ks & 1) * 16;
            const uint32_t bufA = buf + sub * 10240;
            const uint32_t bufB = buf + 20480 + sub * 10240;
            uint32_t A0[4], A1[4];
            fragA(A0, bufA, wm * 32,      k0, lane);
            fragA(A1, bufA, wm * 32 + 16, k0, lane);
#pragma unroll
            for (int p = 0; p < 4; p++) {
                const int nb = wn * 64 + p * 16;
                uint32_t Fb[4];
                fragB2(Fb, bufB, nb, k0, lane);
                const int q = p * 2;
                MMA(cc[0][q],   A0, Fb);
                MMA(cc[1][q],   A1, Fb);
                MMA(cc[0][q+1], A0, Fb + 2);
                MMA(cc[1][q+1], A1, Fb + 2);
            }
        }
    }

    // epilogue: scale by probs, write fp32 out
#pragma unroll
    for (int mt = 0; mt < 2; mt++)
#pragma unroll
        for (int half = 0; half < 2; half++) {
            const int r = wm * 32 + mt * 16 + half * 8 + (lane >> 2);
            if (r < nrows) {
                const float p = probs[row0 + r];
                float* op = out + (size_t)(row0 + r) * HID + n0 + wn * 64;
#pragma unroll
                for (int nt = 0; nt < 8; nt++) {
                    const int col = nt * 8 + (lane & 3) * 2;
                    float2 v;
                    v.x = p * cc[mt][nt][half * 2];
                    v.y = p * cc[mt][nt][half * 2 + 1];
                    *(float2*)(op + col) = v;
                }
            }
        }
}

// ---------------------------------------------------------------------------
// Launch. Streams/events are created ONCE on the first call (correctness run,
// before the harness's pre-capture memory baseline) and reused every call —
// no per-call allocation, so all memory checkpoints see delta 0.
//
// Dependency graph (events; all capturable):
//   s0: gu_t(half0) ──────────────→ gateup(half0) ───────┐
//   s2: convert_x ─eX─(both gateups)  transpose_d ─eD─┐  │
//   s3: (after eG0) gu_t(half1) ──→ gateup(half1) ─eH1┼──┴→ k_down (s0)
// ---------------------------------------------------------------------------
extern "C" void kernel_launch(void* const* d_in, const int* in_sizes, int n_in,
                              void* d_out, int out_size) {
    const float* x     = (const float*)d_in[0];
    const float* probs = (const float*)d_in[1];
    const float* wg    = (const float*)d_in[2];
    const float* wu    = (const float*)d_in[3];
    const float* wd    = (const float*)d_in[4];
    const int*   tpe   = (const int*)d_in[5];
    float*       out   = (float*)d_out;

    static cudaStream_t s2 = nullptr, s3 = nullptr;
    static cudaEvent_t eFork = nullptr, eX = nullptr, eD = nullptr,
                       eG0 = nullptr, eH1 = nullptr;
    if (s2 == nullptr) {
        cudaFuncSetAttribute(k_gateup, cudaFuncAttributeMaxDynamicSharedMemorySize, GU_SMEM);
        cudaFuncSetAttribute(k_down,   cudaFuncAttributeMaxDynamicSharedMemorySize, DN_SMEM);
        cudaStreamCreateWithFlags(&s2, cudaStreamNonBlocking);
        cudaStreamCreateWithFlags(&s3, cudaStreamNonBlocking);
        cudaEventCreateWithFlags(&eFork, cudaEventDisableTiming);
        cudaEventCreateWithFlags(&eX,    cudaEventDisableTiming);
        cudaEventCreateWithFlags(&eD,    cudaEventDisableTiming);
        cudaEventCreateWithFlags(&eG0,   cudaEventDisableTiming);
        cudaEventCreateWithFlags(&eH1,   cudaEventDisableTiming);
    }

    dim3 tb(16, 16);

    cudaEventRecord(eFork, 0);
    cudaStreamWaitEvent(s2, eFork, 0);
    cudaStreamWaitEvent(s3, eFork, 0);

    // s2: x conversion (+ tile table), then down-weight transpose
    convert_x<<<1024, 256, 0, s2>>>(x, tpe);
    cudaEventRecord(eX, s2);
    transpose_cvt_d<<<dim3(INTER / 64, HID / 32, NE), tb, 0, s2>>>(wd);
    cudaEventRecord(eD, s2);

    // s0: first half of gate/up weights, then its GEMM half
    transpose_cvt_gu<<<dim3(HID / 64, NHALF / 32, 2 * NE), tb>>>(wg, wu, 0);
    cudaEventRecord(eG0, 0);
    cudaStreamWaitEvent(0, eX, 0);
    k_gateup<<<dim3(NHALF / 64, MAXGRIDY), 256, GU_SMEM>>>(0);

    // s3: second half transpose (overlaps gateup half0), then its GEMM half
    cudaStreamWaitEvent(s3, eG0, 0);
    transpose_cvt_gu<<<dim3(HID / 64, NHALF / 32, 2 * NE), tb, 0, s3>>>(wg, wu, NHALF);
    cudaStreamWaitEvent(s3, eX, 0);
    k_gateup<<<dim3(NHALF / 64, MAXGRIDY), 256, GU_SMEM, s3>>>(NHALF);
    cudaEventRecord(eH1, s3);

    // s0: down waits on everything
    cudaStreamWaitEvent(0, eH1, 0);
    cudaStreamWaitEvent(0, eD, 0);
    k_down<<<dim3(HID / 128, MAXGRIDY), 256, DN_SMEM>>>(probs, out);
}